// round 3
// baseline (speedup 1.0000x reference)
#include <cuda_runtime.h>
#include <math.h>

// ---------------------------------------------------------------------------
// SineLSTM persistent kernel — 2-layer LSTM, H=512, B=128, T=512, F=64.
// Weight-stationary in SMEM, grid barriers between phases, f32x2 FFMA2 inner
// loop, cp.async.cg double-buffered h streaming (L1-bypassing).
// ---------------------------------------------------------------------------

#define NCTA 128
#define NTHR 128
#define HID  512
#define BAT  128

typedef unsigned long long ull;

// ---------------- persistent device state (no allocations allowed) ---------
__device__ __align__(16) float g_h1[2][HID * BAT];   // [buf][k][b]
__device__ __align__(16) float g_h2[2][HID * BAT];
__device__ __align__(16) float g_xT[HID * BAT];      // x transposed: [t][b] (T<=512)
__device__ __align__(16) float g_xfeed[BAT];
__device__ volatile unsigned g_arrive[NCTA];
__device__ volatile unsigned g_sense;

// ---------------- f32x2 helpers --------------------------------------------
__device__ __forceinline__ ull fma2(ull a, ull b, ull c) {
    ull d;
    asm("fma.rn.f32x2 %0, %1, %2, %3;" : "=l"(d) : "l"(a), "l"(b), "l"(c));
    return d;
}
__device__ __forceinline__ ull dup2(float x) {
    ull d;
    asm("mov.b64 %0, {%1, %1};" : "=l"(d) : "f"(x));
    return d;
}
__device__ __forceinline__ ull pack2(float lo, float hi) {   // cold path
    return (ull)__float_as_uint(lo) | ((ull)__float_as_uint(hi) << 32);
}
__device__ __forceinline__ float lo2(ull a) { return __uint_as_float((unsigned)(a & 0xffffffffull)); }
__device__ __forceinline__ float hi2(ull a) { return __uint_as_float((unsigned)(a >> 32)); }

// ---------------- grid barrier (flag array, no atomic serialization) -------
__device__ __forceinline__ void grid_barrier(unsigned barno) {
    __threadfence();
    __syncthreads();
    if (threadIdx.x == 0) g_arrive[blockIdx.x] = barno;   // volatile -> L2
    if (blockIdx.x == 0) {
        unsigned v;
        do { v = g_arrive[threadIdx.x]; } while (__syncthreads_and(v >= barno) == 0);
        if (threadIdx.x == 0) g_sense = barno;
        __syncthreads();
    } else {
        if (threadIdx.x == 0) { while (g_sense < barno) {} }
        __syncthreads();
    }
    __threadfence();
}

// ---------------- cp.async staging: one 32KB chunk = 64 k-rows x 128 b -----
__device__ __forceinline__ void stage_chunk(float* dst, const float* __restrict__ src, int tid) {
    unsigned d = (unsigned)__cvta_generic_to_shared(dst) + (unsigned)tid * 16u;
    const float4* s = (const float4*)src + tid;
#pragma unroll
    for (int i = 0; i < 16; ++i) {
        asm volatile("cp.async.cg.shared.global [%0], [%1], 16;"
                     :: "r"(d + (unsigned)i * 2048u), "l"(s + i * 128) : "memory");
    }
    asm volatile("cp.async.commit_group;" ::: "memory");
}

// ---------------- one GEMM pass: acc += W[16 gate rows] * h[512][128] ------
__device__ __forceinline__ void gemm_pass(ull* aif, ull* ago,
                                          const float* __restrict__ wsm,
                                          const float* __restrict__ hsrc,
                                          float* hs, int uu, int lane, int tid) {
    stage_chunk(hs, hsrc, tid);
#pragma unroll 1
    for (int c = 0; c < 8; ++c) {
        __syncthreads();                       // buffer (c+1)&1 free for reuse
        if (c < 7) {
            stage_chunk(hs + ((c + 1) & 1) * 8192, hsrc + (c + 1) * 8192, tid);
            asm volatile("cp.async.wait_group 1;" ::: "memory");
        } else {
            asm volatile("cp.async.wait_group 0;" ::: "memory");
        }
        __syncthreads();                       // chunk c fully staged (all threads)
        const float* cur = hs + (c & 1) * 8192;
        const float* wk  = wsm + uu * 2048 + c * 256;
#pragma unroll 8
        for (int k = 0; k < 64; ++k) {
            float4 hv = *(const float4*)(cur + k * 128 + lane * 4);
            ulonglong2 wp = *(const ulonglong2*)(wk + k * 4);   // (wi,wf),(wg,wo) broadcast
            ull h0 = dup2(hv.x), h1 = dup2(hv.y), h2 = dup2(hv.z), h3 = dup2(hv.w);
            aif[0] = fma2(h0, wp.x, aif[0]);  ago[0] = fma2(h0, wp.y, ago[0]);
            aif[1] = fma2(h1, wp.x, aif[1]);  ago[1] = fma2(h1, wp.y, ago[1]);
            aif[2] = fma2(h2, wp.x, aif[2]);  ago[2] = fma2(h2, wp.y, ago[2]);
            aif[3] = fma2(h3, wp.x, aif[3]);  ago[3] = fma2(h3, wp.y, ago[3]);
        }
    }
}

// ---------------- activations + cell update --------------------------------
__device__ __forceinline__ void cell_update(const ull* aif, const ull* ago,
                                            float* cr, float* hj) {
#pragma unroll
    for (int j = 0; j < 4; ++j) {
        float gi = lo2(aif[j]), gf = hi2(aif[j]);
        float gg = lo2(ago[j]), go = hi2(ago[j]);
        float ii = 1.f / (1.f + expf(-gi));
        float ff = 1.f / (1.f + expf(-gf));
        float g  = tanhf(gg);
        float oo = 1.f / (1.f + expf(-go));
        cr[j] = ff * cr[j] + ii * g;
        hj[j] = oo * tanhf(cr[j]);
    }
}

// ---------------- reset / transpose kernel (runs before every main launch) -
__global__ void reset_kernel(const float* __restrict__ x, int T) {
    int idx = blockIdx.x * blockDim.x + threadIdx.x;
    if (idx < HID * BAT) {
        g_h1[0][idx] = 0.f; g_h1[1][idx] = 0.f;
        g_h2[0][idx] = 0.f; g_h2[1][idx] = 0.f;
    }
    int n = BAT * T;
    if (idx < n) {                 // x[b][t] -> xT[t][b]
        int b = idx / T, t = idx - b * T;
        g_xT[t * BAT + b] = x[idx];
    }
    if (idx < NCTA) { g_arrive[idx] = 0; }
    if (idx < BAT)  { g_xfeed[idx] = 0.f; }
    if (idx == 0)   { g_sense = 0; }
}

// ---------------- main persistent kernel -----------------------------------
__global__ void __launch_bounds__(NTHR, 1)
lstm_main(const float* __restrict__ Wih1, const float* __restrict__ Whh1,
          const float* __restrict__ bih1, const float* __restrict__ bhh1,
          const float* __restrict__ Wih2, const float* __restrict__ Whh2,
          const float* __restrict__ bih2, const float* __restrict__ bhh2,
          const float* __restrict__ Wout, const float* __restrict__ bout,
          float* __restrict__ out, int T, int F) {
    extern __shared__ float sm[];
    float* w1  = sm;            // 8192 floats: [4 units][512 k][4 gates]
    float* wi2 = sm + 8192;
    float* wh2 = sm + 16384;
    float* hs  = sm + 24576;    // 2 x 8192 floats staging
    __shared__ float s_b1[16], s_b2[16], s_wx[16], s_red[4];

    const int tid = threadIdx.x, lane = tid & 31, uu = tid >> 5, bid = blockIdx.x;

    // one-time weight load into SMEM (gate rows: gi*512 + unit)
    for (int idx = tid; idx < 8192; idx += NTHR) {
        int wuu = idx >> 11, rem = idx & 2047, k = rem >> 2, gi = rem & 3;
        int row = gi * HID + bid * 4 + wuu;
        w1[idx]  = Whh1[row * HID + k];
        wi2[idx] = Wih2[row * HID + k];
        wh2[idx] = Whh2[row * HID + k];
    }
    if (tid < 16) {
        int tu = tid >> 2, gi = tid & 3;
        int row = gi * HID + bid * 4 + tu;
        s_b1[tid] = bih1[row] + bhh1[row];
        s_b2[tid] = bih2[row] + bhh2[row];
        s_wx[tid] = Wih1[row];              // W_ih1 is [4H, 1]
    }
    __syncthreads();

    const float bi1 = s_b1[uu*4+0], bf1 = s_b1[uu*4+1], bg1 = s_b1[uu*4+2], bo1 = s_b1[uu*4+3];
    const float bi2 = s_b2[uu*4+0], bf2 = s_b2[uu*4+1], bg2 = s_b2[uu*4+2], bo2 = s_b2[uu*4+3];
    const float wxi = s_wx[uu*4+0], wxf = s_wx[uu*4+1], wxg = s_wx[uu*4+2], wxo = s_wx[uu*4+3];
    const float bo_out = __ldg(bout);
    const int u = bid * 4 + uu;
    const int TF = T + F;

    float c1r[4] = {0, 0, 0, 0}, c2r[4] = {0, 0, 0, 0};
    float hj[4];
    int p = 0, q = 0;
    unsigned barno = 0;

    for (int t = 0; t < TF; ++t) {
        // ---- Phase A: layer 1 -------------------------------------------
        float4 xv = (t < T) ? __ldcg((const float4*)(g_xT + t * BAT + lane * 4))
                            : __ldcg((const float4*)(g_xfeed + lane * 4));
        ull aif[4], ago[4];
        aif[0] = pack2(fmaf(xv.x, wxi, bi1), fmaf(xv.x, wxf, bf1));
        ago[0] = pack2(fmaf(xv.x, wxg, bg1), fmaf(xv.x, wxo, bo1));
        aif[1] = pack2(fmaf(xv.y, wxi, bi1), fmaf(xv.y, wxf, bf1));
        ago[1] = pack2(fmaf(xv.y, wxg, bg1), fmaf(xv.y, wxo, bo1));
        aif[2] = pack2(fmaf(xv.z, wxi, bi1), fmaf(xv.z, wxf, bf1));
        ago[2] = pack2(fmaf(xv.z, wxg, bg1), fmaf(xv.z, wxo, bo1));
        aif[3] = pack2(fmaf(xv.w, wxi, bi1), fmaf(xv.w, wxf, bf1));
        ago[3] = pack2(fmaf(xv.w, wxg, bg1), fmaf(xv.w, wxo, bo1));

        gemm_pass(aif, ago, w1, g_h1[p], hs, uu, lane, tid);
        cell_update(aif, ago, c1r, hj);
        __stcg((float4*)(g_h1[p ^ 1] + u * BAT + lane * 4),
               make_float4(hj[0], hj[1], hj[2], hj[3]));
        grid_barrier(++barno);

        // ---- Phase B: layer 2 (two accumulating passes) ------------------
        aif[0] = pack2(bi2, bf2); ago[0] = pack2(bg2, bo2);
        aif[1] = aif[0]; ago[1] = ago[0];
        aif[2] = aif[0]; ago[2] = ago[0];
        aif[3] = aif[0]; ago[3] = ago[0];
        gemm_pass(aif, ago, wi2, g_h1[p ^ 1], hs, uu, lane, tid);
        gemm_pass(aif, ago, wh2, g_h2[q],     hs, uu, lane, tid);
        cell_update(aif, ago, c2r, hj);
        __stcg((float4*)(g_h2[q ^ 1] + u * BAT + lane * 4),
               make_float4(hj[0], hj[1], hj[2], hj[3]));
        grid_barrier(++barno);

        // ---- Phase C: output projection (CTA bid == batch element) -------
        {
            const float* h2n = g_h2[q ^ 1];
            float part = 0.f;
#pragma unroll
            for (int jj = 0; jj < 4; ++jj) {
                int k = tid + jj * NTHR;
                part += __ldcg(h2n + k * BAT + bid) * __ldg(Wout + k);
            }
#pragma unroll
            for (int s = 16; s; s >>= 1) part += __shfl_xor_sync(0xffffffffu, part, s);
            if (lane == 0) s_red[uu] = part;
            __syncthreads();
            if (tid == 0) {
                float o = s_red[0] + s_red[1] + s_red[2] + s_red[3] + bo_out;
                out[bid * TF + t] = o;
                __stcg(g_xfeed + bid, o);
            }
        }
        // barrier only needed once the feedback path consumes 'out'
        if (t >= T - 1) grid_barrier(++barno);
        else            __syncthreads();       // s_red reuse
        p ^= 1; q ^= 1;
    }
}

// ---------------------------------------------------------------------------
extern "C" void kernel_launch(void* const* d_in, const int* in_sizes, int n_in,
                              void* d_out, int out_size) {
    const float* x    = (const float*)d_in[0];
    // d_in[1] = "future" (derived from out_size instead)
    const float* Wih1 = (const float*)d_in[2];
    const float* Whh1 = (const float*)d_in[3];
    const float* bih1 = (const float*)d_in[4];
    const float* bhh1 = (const float*)d_in[5];
    const float* Wih2 = (const float*)d_in[6];
    const float* Whh2 = (const float*)d_in[7];
    const float* bih2 = (const float*)d_in[8];
    const float* bhh2 = (const float*)d_in[9];
    const float* Wout = (const float*)d_in[10];
    const float* bout = (const float*)d_in[11];

    int T  = in_sizes[0] / BAT;       // 512
    int TF = out_size / BAT;          // 576
    int F  = TF - T;                  // 64

    cudaFuncSetAttribute(lstm_main, cudaFuncAttributeMaxDynamicSharedMemorySize, 163840);

    reset_kernel<<<256, 256>>>(x, T);
    lstm_main<<<NCTA, NTHR, 163840>>>(Wih1, Whh1, bih1, bhh1,
                                      Wih2, Whh2, bih2, bhh2,
                                      Wout, bout, (float*)d_out, T, F);
}